// round 1
// baseline (speedup 1.0000x reference)
#include <cuda_runtime.h>
#include <cuda_bf16.h>
#include <cstdint>

// ---------------------------------------------------------------------------
// SinkhornMatch: proj -> Kn GEMM (+exp epilogue) -> linear-domain Sinkhorn
// (100 iters, matrix L2-resident) -> scores -> mutual top-3 assignment.
// ---------------------------------------------------------------------------

#define MDIM 4096
#define NDIM 4096
#define KDIM 512
#define MP1  4097
#define KSTRIDE 4104            // row stride of the exp-matrix (16B aligned rows)

static const float INV_S  = 0.21022410381342865f;   // 1 / 512^0.25
#define MU_REG   (1.0f/8192.0f)
#define MU_BIN   0.5f
#define THRESH   0.05f

// ------------------------- device scratch (no allocs) ----------------------
__device__ float g_m0[(size_t)MDIM * KDIM];
__device__ float g_m1[(size_t)NDIM * KDIM];
__device__ float g_K [(size_t)MP1 * KSTRIDE];   // exp(Z0), 67.3 MB
__device__ float g_U [MP1];
__device__ float g_V [MP1];
__device__ float g_t3r[MDIM];
__device__ float g_t3c[NDIM];
__device__ float g_cp[8 * NDIM * 3];            // column top-3 partials

// ------------------------------- SGEMM NT ----------------------------------
// C(MxN) = A(MxK,row) * B(NxK,row)^T.  BM=BN=128, BK=16, 256 thr, 8x8/thread.
// MODE 0: proj -> g_m0   MODE 1: proj -> g_m1   MODE 2: Kn -> C + exp -> g_K
template <int MODE>
__global__ void __launch_bounds__(256)
sgemm_nt(const float* __restrict__ Ap, const float* __restrict__ Bp,
         const float* __restrict__ bias, float* __restrict__ C)
{
    constexpr int BM = 128, BN = 128, BK = 16;
    constexpr int N = (MODE == 2) ? NDIM : KDIM;
    constexpr int K = KDIM;

    const float* A = (MODE == 2) ? (const float*)g_m0 : Ap;
    const float* B = (MODE == 2) ? (const float*)g_m1 : Bp;

    __shared__ __align__(16) float As[BK][BM];
    __shared__ __align__(16) float Bs[BK][BN];

    const int tid = threadIdx.x;
    const int bm = blockIdx.y * BM;
    const int bn = blockIdx.x * BN;
    const int tx = tid % 16, ty = tid / 16;

    float acc[8][8];
#pragma unroll
    for (int i = 0; i < 8; i++)
#pragma unroll
        for (int j = 0; j < 8; j++) acc[i][j] = 0.f;

    const int lr = tid / 4;          // 0..63
    const int lc = (tid % 4) * 4;    // 0,4,8,12

    for (int k0 = 0; k0 < K; k0 += BK) {
#pragma unroll
        for (int h = 0; h < 2; h++) {
            int row = lr + h * 64;
            float4 a4 = *(const float4*)(A + (size_t)(bm + row) * K + k0 + lc);
            As[lc + 0][row] = a4.x; As[lc + 1][row] = a4.y;
            As[lc + 2][row] = a4.z; As[lc + 3][row] = a4.w;
            float4 b4 = *(const float4*)(B + (size_t)(bn + row) * K + k0 + lc);
            Bs[lc + 0][row] = b4.x; Bs[lc + 1][row] = b4.y;
            Bs[lc + 2][row] = b4.z; Bs[lc + 3][row] = b4.w;
        }
        __syncthreads();
#pragma unroll
        for (int kk = 0; kk < BK; kk++) {
            float ar[8], br[8];
#pragma unroll
            for (int i = 0; i < 8; i++) ar[i] = As[kk][ty * 8 + i];
#pragma unroll
            for (int j = 0; j < 8; j++) br[j] = Bs[kk][tx * 8 + j];
#pragma unroll
            for (int i = 0; i < 8; i++)
#pragma unroll
                for (int j = 0; j < 8; j++) acc[i][j] += ar[i] * br[j];
        }
        __syncthreads();
    }

#pragma unroll
    for (int i = 0; i < 8; i++) {
        int gm = bm + ty * 8 + i;
#pragma unroll
        for (int j = 0; j < 8; j++) {
            int gn = bn + tx * 8 + j;
            if (MODE == 2) {
                float c = acc[i][j];
                C[(size_t)gm * NDIM + gn] = c;
                g_K[(size_t)gm * KSTRIDE + gn] = expf(c);
            } else {
                float c = (acc[i][j] + bias[gn]) * INV_S;
                float* dst = (MODE == 0) ? g_m0 : g_m1;
                dst[(size_t)gm * KDIM + gn] = c;
            }
        }
    }
}

// --------------------------- init dustbin + V ------------------------------
__global__ void init_kernel(const float* __restrict__ alphap)
{
    float ea = expf(alphap[0]);
    int t = blockIdx.x * 256 + threadIdx.x;
    if (t < MP1) {
        g_K[(size_t)t * KSTRIDE + NDIM] = ea;          // dustbin column
        g_K[(size_t)MDIM * KSTRIDE + t] = ea;          // dustbin row
        g_V[t] = 1.0f;
    }
}

// --------------------------- Sinkhorn u-pass -------------------------------
// U[i] = mu_i / sum_j K[i,j] * V[j].  8 rows/block (1 warp / row).
__global__ void __launch_bounds__(256) u_pass()
{
    __shared__ __align__(16) float sV[MP1 + 3];
    int tid = threadIdx.x;
    for (int j = tid; j < MP1; j += 256) sV[j] = g_V[j];
    __syncthreads();

    int warp = tid >> 5, lane = tid & 31;
    int i = blockIdx.x * 8 + warp;
    if (i >= MP1) return;
    const float* row = g_K + (size_t)i * KSTRIDE;

    float a0 = 0.f, a1 = 0.f;
    for (int j = lane * 4; j < NDIM; j += 256) {
        float4 k0 = *(const float4*)(row + j);
        float4 v0 = *(const float4*)(sV + j);
        a0 += k0.x * v0.x + k0.y * v0.y + k0.z * v0.z + k0.w * v0.w;
        float4 k1 = *(const float4*)(row + j + 128);
        float4 v1 = *(const float4*)(sV + j + 128);
        a1 += k1.x * v1.x + k1.y * v1.y + k1.z * v1.z + k1.w * v1.w;
    }
    float acc = a0 + a1;
    if (lane == 0) acc += row[NDIM] * sV[NDIM];
#pragma unroll
    for (int o = 16; o; o >>= 1) acc += __shfl_xor_sync(0xffffffffu, acc, o);
    if (lane == 0) g_U[i] = ((i < MDIM) ? MU_REG : MU_BIN) / acc;
}

// --------------------------- Sinkhorn v-pass -------------------------------
// V[j] = nu_j / sum_i K[i,j] * U[i].  32 cols/block, 8 row-groups.
__global__ void __launch_bounds__(256) v_pass()
{
    __shared__ __align__(16) float sU[MP1 + 3];
    __shared__ float red[8][32];
    int tid = threadIdx.x;
    for (int i = tid; i < MP1; i += 256) sU[i] = g_U[i];
    __syncthreads();

    int c = tid & 31, r = tid >> 5;
    int col = blockIdx.x * 32 + c;
    float acc[8] = {0, 0, 0, 0, 0, 0, 0, 0};
    if (col < MP1) {
        int i = r;
        for (; i + 56 < MP1; i += 64) {
#pragma unroll
            for (int u = 0; u < 8; u++)
                acc[u] += g_K[(size_t)(i + u * 8) * KSTRIDE + col] * sU[i + u * 8];
        }
        for (; i < MP1; i += 8)
            acc[0] += g_K[(size_t)i * KSTRIDE + col] * sU[i];
    }
    float a = ((acc[0] + acc[1]) + (acc[2] + acc[3])) +
              ((acc[4] + acc[5]) + (acc[6] + acc[7]));
    red[r][c] = a;
    __syncthreads();
    if (tid < 32) {
        float s = 0.f;
#pragma unroll
        for (int r2 = 0; r2 < 8; r2++) s += red[r2][tid];
        int col2 = blockIdx.x * 32 + tid;
        if (col2 < MP1) g_V[col2] = ((col2 < NDIM) ? MU_REG : MU_BIN) / s;
    }
}

// ------------------------------- scores ------------------------------------
__global__ void scores_kernel(float* __restrict__ outS)
{
    int i = blockIdx.x;
    float ui = g_U[i] * 8192.0f;
    const float* krow = g_K + (size_t)i * KSTRIDE;
    float* srow = outS + (size_t)i * MP1;
    for (int j = threadIdx.x; j < MP1; j += 256) srow[j] = krow[j] * ui * g_V[j];
}

// ------------------------------ top-3 utils --------------------------------
__device__ __forceinline__ void top3_ins(float v, float& t0, float& t1, float& t2)
{
    if (v > t2) {
        if (v > t1) {
            t2 = t1;
            if (v > t0) { t1 = t0; t0 = v; } else t1 = v;
        } else t2 = v;
    }
}

__global__ void row_top3_kernel(const float* __restrict__ S)
{
    int i = blockIdx.x;
    const float* row = S + (size_t)i * MP1;
    float t0 = -1e30f, t1 = -1e30f, t2 = -1e30f;
    for (int j = threadIdx.x; j < NDIM; j += 256) top3_ins(row[j], t0, t1, t2);
#pragma unroll
    for (int o = 16; o; o >>= 1) {
        float b0 = __shfl_xor_sync(0xffffffffu, t0, o);
        float b1 = __shfl_xor_sync(0xffffffffu, t1, o);
        float b2 = __shfl_xor_sync(0xffffffffu, t2, o);
        top3_ins(b0, t0, t1, t2); top3_ins(b1, t0, t1, t2); top3_ins(b2, t0, t1, t2);
    }
    __shared__ float s3[8][3];
    if ((threadIdx.x & 31) == 0) {
        int w = threadIdx.x >> 5;
        s3[w][0] = t0; s3[w][1] = t1; s3[w][2] = t2;
    }
    __syncthreads();
    if (threadIdx.x == 0) {
        float r0 = s3[0][0], r1 = s3[0][1], r2 = s3[0][2];
        for (int w = 1; w < 8; w++) {
            top3_ins(s3[w][0], r0, r1, r2);
            top3_ins(s3[w][1], r0, r1, r2);
            top3_ins(s3[w][2], r0, r1, r2);
        }
        g_t3r[i] = r2;
    }
}

__global__ void col_top3_part(const float* __restrict__ S)
{
    int c = threadIdx.x & 31, r = threadIdx.x >> 5;
    int col = blockIdx.x * 32 + c;
    int i0 = blockIdx.y * 512;
    float t0 = -1e30f, t1 = -1e30f, t2 = -1e30f;
    for (int i = i0 + r; i < i0 + 512; i += 8)
        top3_ins(S[(size_t)i * MP1 + col], t0, t1, t2);
    __shared__ float s3[8][32][3];
    s3[r][c][0] = t0; s3[r][c][1] = t1; s3[r][c][2] = t2;
    __syncthreads();
    if (threadIdx.x < 32) {
        int cc = threadIdx.x;
        float r0 = s3[0][cc][0], r1 = s3[0][cc][1], r2 = s3[0][cc][2];
        for (int w = 1; w < 8; w++) {
            top3_ins(s3[w][cc][0], r0, r1, r2);
            top3_ins(s3[w][cc][1], r0, r1, r2);
            top3_ins(s3[w][cc][2], r0, r1, r2);
        }
        int colg = blockIdx.x * 32 + cc;
        size_t base = ((size_t)blockIdx.y * NDIM + colg) * 3;
        g_cp[base + 0] = r0; g_cp[base + 1] = r1; g_cp[base + 2] = r2;
    }
}

__global__ void col_top3_red()
{
    int col = blockIdx.x * 256 + threadIdx.x;
    if (col >= NDIM) return;
    float r0 = -1e30f, r1 = -1e30f, r2 = -1e30f;
    for (int rc = 0; rc < 8; rc++) {
        size_t base = ((size_t)rc * NDIM + col) * 3;
        top3_ins(g_cp[base + 0], r0, r1, r2);
        top3_ins(g_cp[base + 1], r0, r1, r2);
        top3_ins(g_cp[base + 2], r0, r1, r2);
    }
    g_t3c[col] = r2;
}

__global__ void assign_kernel(const float* __restrict__ S, float* __restrict__ outA)
{
    int i = blockIdx.x;
    float tr = g_t3r[i];
    const float* row = S + (size_t)i * MP1;
    float* arow = outA + (size_t)i * NDIM;
    for (int j = threadIdx.x; j < NDIM; j += 256) {
        float a = row[j];
        arow[j] = (a >= tr && a >= g_t3c[j] && a > THRESH) ? 1.0f : 0.0f;
    }
}

// ------------------------------- launcher ----------------------------------
extern "C" void kernel_launch(void* const* d_in, const int* in_sizes, int n_in,
                              void* d_out, int out_size)
{
    const float* desc0 = (const float*)d_in[0];
    const float* desc1 = (const float*)d_in[1];
    const float* W     = (const float*)d_in[2];
    const float* bias  = (const float*)d_in[3];
    const float* alpha = (const float*)d_in[4];

    float* outKn = (float*)d_out;
    float* outS  = outKn + (size_t)MDIM * NDIM;
    float* outA  = outS + (size_t)MP1 * MP1;

    // projections: (desc @ W^T + b) / s
    sgemm_nt<0><<<dim3(KDIM / 128, MDIM / 128), 256>>>(desc0, W, bias, nullptr);
    sgemm_nt<1><<<dim3(KDIM / 128, NDIM / 128), 256>>>(desc1, W, bias, nullptr);

    // dustbin row/col + V init (independent of Kn block of g_K)
    init_kernel<<<(MP1 + 255) / 256, 256>>>(alpha);

    // Kn = m0s @ m1s^T  (+ exp epilogue into g_K)
    sgemm_nt<2><<<dim3(NDIM / 128, MDIM / 128), 256>>>(nullptr, nullptr, nullptr, outKn);

    // linear-domain Sinkhorn, 100 iterations
    for (int it = 0; it < 100; it++) {
        u_pass<<<(MP1 + 7) / 8, 256>>>();
        v_pass<<<(MP1 + 31) / 32, 256>>>();
    }

    // scores = K * U * V * (m+n)
    scores_kernel<<<MP1, 256>>>(outS);

    // mutual top-3 + threshold
    row_top3_kernel<<<MDIM, 256>>>(outS);
    col_top3_part<<<dim3(NDIM / 32, 8), 256>>>(outS);
    col_top3_red<<<(NDIM + 255) / 256, 256>>>();
    assign_kernel<<<MDIM, 256>>>(outS, outA);
}

// round 2
// speedup vs baseline: 1.2281x; 1.2281x over previous
#include <cuda_runtime.h>
#include <cuda_fp16.h>
#include <cuda_bf16.h>
#include <cstdint>

// ---------------------------------------------------------------------------
// SinkhornMatch: proj -> Kn GEMM (+exp epilogue fp32+fp16) ->
// persistent linear-domain Sinkhorn (100 iters, fp16 matrix, grid barrier) ->
// scores(+row top3) -> col top3 -> assignment.
// ---------------------------------------------------------------------------

#define MDIM 4096
#define NDIM 4096
#define KDIM 512
#define MP1  4097
#define KSTRIDE 4104            // row stride (fp32 rows 16B aligned, fp16 rows 8B aligned)

static const float INV_S  = 0.21022410381342865f;   // 1 / 512^0.25
#define MU_REG   (1.0f/8192.0f)
#define MU_BIN   0.5f
#define THRESH   0.05f

// ------------------------- device scratch (no allocs) ----------------------
__device__ float  g_m0[(size_t)MDIM * KDIM];
__device__ float  g_m1[(size_t)NDIM * KDIM];
__device__ float  g_K [(size_t)MP1 * KSTRIDE];   // exp(Z0) fp32 (for scores)
__device__ __half g_Kh[(size_t)MP1 * KSTRIDE];   // exp(Z0) fp16 (for Sinkhorn)
__device__ float  g_U [MP1];
__device__ float  g_V [MP1];
__device__ float  g_t3r[MDIM];
__device__ float  g_t3c[NDIM];
__device__ float  g_cp[8 * NDIM * 3];            // column top-3 partials
__device__ int    g_barc, g_barg;                // grid barrier state

// ------------------------------- SGEMM NT ----------------------------------
// C(MxN) = A(MxK,row) * B(NxK,row)^T. BM=BN=128, BK=16, 256 thr, 8x8/thread,
// double-buffered smem (one __syncthreads per K-step).
// MODE 0: proj -> g_m0   MODE 1: proj -> g_m1   MODE 2: Kn -> C + exp -> g_K/g_Kh
template <int MODE>
__global__ void __launch_bounds__(256)
sgemm_nt(const float* __restrict__ Ap, const float* __restrict__ Bp,
         const float* __restrict__ bias, float* __restrict__ C)
{
    constexpr int BM = 128, BN = 128, BK = 16;
    constexpr int K = KDIM;

    const float* A = (MODE == 2) ? (const float*)g_m0 : Ap;
    const float* B = (MODE == 2) ? (const float*)g_m1 : Bp;

    __shared__ __align__(16) float As[2][BK][BM];
    __shared__ __align__(16) float Bs[2][BK][BN];

    const int tid = threadIdx.x;
    const int bm = blockIdx.y * BM;
    const int bn = blockIdx.x * BN;
    const int tx = tid % 16, ty = tid / 16;
    const int lr = tid / 4;          // 0..63
    const int lc = (tid % 4) * 4;    // 0,4,8,12

    float acc[8][8];
#pragma unroll
    for (int i = 0; i < 8; i++)
#pragma unroll
        for (int j = 0; j < 8; j++) acc[i][j] = 0.f;

    float4 pa[2], pb[2];
    // prologue: tile k0=0 -> buffer 0
#pragma unroll
    for (int h = 0; h < 2; h++) {
        pa[h] = *(const float4*)(A + (size_t)(bm + lr + h * 64) * K + lc);
        pb[h] = *(const float4*)(B + (size_t)(bn + lr + h * 64) * K + lc);
    }
#pragma unroll
    for (int h = 0; h < 2; h++) {
        int row = lr + h * 64;
        As[0][lc + 0][row] = pa[h].x; As[0][lc + 1][row] = pa[h].y;
        As[0][lc + 2][row] = pa[h].z; As[0][lc + 3][row] = pa[h].w;
        Bs[0][lc + 0][row] = pb[h].x; Bs[0][lc + 1][row] = pb[h].y;
        Bs[0][lc + 2][row] = pb[h].z; Bs[0][lc + 3][row] = pb[h].w;
    }
    __syncthreads();

    int buf = 0;
    for (int k0 = 0; k0 < K; k0 += BK) {
        if (k0 + BK < K) {
#pragma unroll
            for (int h = 0; h < 2; h++) {
                pa[h] = *(const float4*)(A + (size_t)(bm + lr + h * 64) * K + k0 + BK + lc);
                pb[h] = *(const float4*)(B + (size_t)(bn + lr + h * 64) * K + k0 + BK + lc);
            }
        }
        const float (*Asb)[BM] = As[buf];
        const float (*Bsb)[BN] = Bs[buf];
#pragma unroll
        for (int kk = 0; kk < BK; kk++) {
            float ar[8], br[8];
#pragma unroll
            for (int i = 0; i < 8; i++) ar[i] = Asb[kk][ty * 8 + i];
#pragma unroll
            for (int j = 0; j < 8; j++) br[j] = Bsb[kk][tx * 8 + j];
#pragma unroll
            for (int i = 0; i < 8; i++)
#pragma unroll
                for (int j = 0; j < 8; j++) acc[i][j] += ar[i] * br[j];
        }
        if (k0 + BK < K) {
            int nb = buf ^ 1;
#pragma unroll
            for (int h = 0; h < 2; h++) {
                int row = lr + h * 64;
                As[nb][lc + 0][row] = pa[h].x; As[nb][lc + 1][row] = pa[h].y;
                As[nb][lc + 2][row] = pa[h].z; As[nb][lc + 3][row] = pa[h].w;
                Bs[nb][lc + 0][row] = pb[h].x; Bs[nb][lc + 1][row] = pb[h].y;
                Bs[nb][lc + 2][row] = pb[h].z; Bs[nb][lc + 3][row] = pb[h].w;
            }
            __syncthreads();
            buf = nb;
        }
    }

#pragma unroll
    for (int i = 0; i < 8; i++) {
        int gm = bm + ty * 8 + i;
#pragma unroll
        for (int j = 0; j < 8; j++) {
            int gn = bn + tx * 8 + j;
            if (MODE == 2) {
                float c = acc[i][j];
                C[(size_t)gm * NDIM + gn] = c;
                float e = expf(c);
                g_K [(size_t)gm * KSTRIDE + gn] = e;
                g_Kh[(size_t)gm * KSTRIDE + gn] = __float2half_rn(e);
            } else {
                float c = (acc[i][j] + bias[gn]) * INV_S;
                float* dst = (MODE == 0) ? g_m0 : g_m1;
                dst[(size_t)gm * KDIM + gn] = c;
            }
        }
    }
}

// --------------------------- init dustbin + V + barrier --------------------
__global__ void init_kernel(const float* __restrict__ alphap)
{
    float ea = expf(alphap[0]);
    __half eh = __float2half_rn(ea);
    int t = blockIdx.x * 256 + threadIdx.x;
    if (t < MP1) {
        g_K [(size_t)t * KSTRIDE + NDIM] = ea;          // dustbin column
        g_K [(size_t)MDIM * KSTRIDE + t] = ea;          // dustbin row
        g_Kh[(size_t)t * KSTRIDE + NDIM] = eh;
        g_Kh[(size_t)MDIM * KSTRIDE + t] = eh;
        g_V[t] = 1.0f;
    }
    if (t == 0) { g_barc = 0; g_barg = 0; }
}

// --------------------------- grid barrier ----------------------------------
__device__ __forceinline__ void gsync(int nb)
{
    __syncthreads();
    if (threadIdx.x == 0) {
        __threadfence();
        int gen = *((volatile int*)&g_barg);
        if (atomicAdd(&g_barc, 1) == nb - 1) {
            g_barc = 0;
            __threadfence();
            atomicExch(&g_barg, gen + 1);
        } else {
            while (*((volatile int*)&g_barg) == gen) { __nanosleep(64); }
        }
        __threadfence();
    }
    __syncthreads();
}

// ------------------- persistent Sinkhorn (100 iterations) ------------------
// u-pass: U[i] = mu_i / sum_j K[i,j] V[j]   (one warp per row)
// v-pass: V[j] = nu_j / sum_i K[i,j] U[i]   (32-col strips, 16 row groups)
__global__ void __launch_bounds__(512)
sinkhorn_persist(int nb)
{
    __shared__ __align__(16) float sW[MP1 + 3];   // V during u-phase, U during v-phase
    __shared__ float sred[16][33];

    const int tid = threadIdx.x;
    const int bid = blockIdx.x;
    const int warp = tid >> 5, lane = tid & 31;

    for (int it = 0; it < 100; it++) {
        // ---- u phase ----
        for (int j = tid; j < MP1; j += 512) sW[j] = __ldcg(g_V + j);
        __syncthreads();

        for (int i = bid * 16 + warp; i < MP1; i += nb * 16) {
            const __half* rowp = g_Kh + (size_t)i * KSTRIDE;
            float acc = 0.f;
#pragma unroll 4
            for (int j = lane * 4; j < NDIM; j += 128) {
                uint2 raw = *(const uint2*)(rowp + j);
                __half2 h0 = *reinterpret_cast<__half2*>(&raw.x);
                __half2 h1 = *reinterpret_cast<__half2*>(&raw.y);
                float2 f0 = __half22float2(h0);
                float2 f1 = __half22float2(h1);
                float4 v = *(const float4*)(sW + j);
                acc += f0.x * v.x + f0.y * v.y + f1.x * v.z + f1.y * v.w;
            }
            if (lane == 0) acc += __half2float(rowp[NDIM]) * sW[NDIM];
#pragma unroll
            for (int o = 16; o; o >>= 1) acc += __shfl_xor_sync(0xffffffffu, acc, o);
            if (lane == 0)
                __stcg(&g_U[i], ((i < MDIM) ? MU_REG : MU_BIN) / acc);
        }
        gsync(nb);

        // ---- v phase ----
        for (int j = tid; j < MP1; j += 512) sW[j] = __ldcg(g_U + j);
        __syncthreads();

        for (int u = bid; u < 129; u += nb) {
            if (u < 128) {
                int col = u * 32 + (tid & 31);
                int rg = tid >> 5;               // 0..15
                const __half* cp = g_Kh + col;
                float acc = 0.f;
                int r = rg;
                for (; r + 48 < MP1; r += 64) {
                    acc += __half2float(cp[(size_t)(r)      * KSTRIDE]) * sW[r];
                    acc += __half2float(cp[(size_t)(r + 16) * KSTRIDE]) * sW[r + 16];
                    acc += __half2float(cp[(size_t)(r + 32) * KSTRIDE]) * sW[r + 32];
                    acc += __half2float(cp[(size_t)(r + 48) * KSTRIDE]) * sW[r + 48];
                }
                for (; r < MP1; r += 16)
                    acc += __half2float(cp[(size_t)r * KSTRIDE]) * sW[r];
                sred[rg][tid & 31] = acc;
                __syncthreads();
                if (tid < 32) {
                    float s = 0.f;
#pragma unroll
                    for (int g = 0; g < 16; g++) s += sred[g][tid];
                    __stcg(&g_V[u * 32 + tid], MU_REG / s);
                }
                __syncthreads();
            } else {
                // dustbin column j = NDIM
                float acc = 0.f;
                for (int r = tid; r < MP1; r += 512)
                    acc += __half2float(g_Kh[(size_t)r * KSTRIDE + NDIM]) * sW[r];
#pragma unroll
                for (int o = 16; o; o >>= 1) acc += __shfl_xor_sync(0xffffffffu, acc, o);
                if ((tid & 31) == 0) sred[0][tid >> 5] = acc;
                __syncthreads();
                if (tid == 0) {
                    float s = 0.f;
#pragma unroll
                    for (int g = 0; g < 16; g++) s += sred[0][g];
                    __stcg(&g_V[NDIM], MU_BIN / s);
                }
                __syncthreads();
            }
        }
        gsync(nb);
    }
}

// ------------------------------ top-3 utils --------------------------------
__device__ __forceinline__ void top3_ins(float v, float& t0, float& t1, float& t2)
{
    if (v > t2) {
        if (v > t1) {
            t2 = t1;
            if (v > t0) { t1 = t0; t0 = v; } else t1 = v;
        } else t2 = v;
    }
}

// ------------------- scores = K*U*V*(m+n)  (+ row top-3) -------------------
__global__ void scores_kernel(float* __restrict__ outS)
{
    int i = blockIdx.x;
    float ui = g_U[i] * 8192.0f;
    const float* krow = g_K + (size_t)i * KSTRIDE;
    float* srow = outS + (size_t)i * MP1;

    float t0 = -1e30f, t1 = -1e30f, t2 = -1e30f;
    for (int j = threadIdx.x; j < MP1; j += 256) {
        float sc = krow[j] * ui * g_V[j];
        srow[j] = sc;
        if (j < NDIM) top3_ins(sc, t0, t1, t2);
    }
    if (i >= MDIM) return;
#pragma unroll
    for (int o = 16; o; o >>= 1) {
        float b0 = __shfl_xor_sync(0xffffffffu, t0, o);
        float b1 = __shfl_xor_sync(0xffffffffu, t1, o);
        float b2 = __shfl_xor_sync(0xffffffffu, t2, o);
        top3_ins(b0, t0, t1, t2); top3_ins(b1, t0, t1, t2); top3_ins(b2, t0, t1, t2);
    }
    __shared__ float s3[8][3];
    if ((threadIdx.x & 31) == 0) {
        int w = threadIdx.x >> 5;
        s3[w][0] = t0; s3[w][1] = t1; s3[w][2] = t2;
    }
    __syncthreads();
    if (threadIdx.x == 0) {
        float r0 = s3[0][0], r1 = s3[0][1], r2 = s3[0][2];
        for (int w = 1; w < 8; w++) {
            top3_ins(s3[w][0], r0, r1, r2);
            top3_ins(s3[w][1], r0, r1, r2);
            top3_ins(s3[w][2], r0, r1, r2);
        }
        g_t3r[i] = r2;
    }
}

// ------------------------------ column top-3 -------------------------------
__global__ void col_top3_part(const float* __restrict__ S)
{
    int c = threadIdx.x & 31, r = threadIdx.x >> 5;
    int col = blockIdx.x * 32 + c;
    int i0 = blockIdx.y * 512;
    float t0 = -1e30f, t1 = -1e30f, t2 = -1e30f;
    for (int i = i0 + r; i < i0 + 512; i += 8)
        top3_ins(S[(size_t)i * MP1 + col], t0, t1, t2);
    __shared__ float s3[8][32][3];
    s3[r][c][0] = t0; s3[r][c][1] = t1; s3[r][c][2] = t2;
    __syncthreads();
    if (threadIdx.x < 32) {
        int cc = threadIdx.x;
        float r0 = s3[0][cc][0], r1 = s3[0][cc][1], r2 = s3[0][cc][2];
        for (int w = 1; w < 8; w++) {
            top3_ins(s3[w][cc][0], r0, r1, r2);
            top3_ins(s3[w][cc][1], r0, r1, r2);
            top3_ins(s3[w][cc][2], r0, r1, r2);
        }
        int colg = blockIdx.x * 32 + cc;
        size_t base = ((size_t)blockIdx.y * NDIM + colg) * 3;
        g_cp[base + 0] = r0; g_cp[base + 1] = r1; g_cp[base + 2] = r2;
    }
}

__global__ void col_top3_red()
{
    int col = blockIdx.x * 256 + threadIdx.x;
    if (col >= NDIM) return;
    float r0 = -1e30f, r1 = -1e30f, r2 = -1e30f;
    for (int rc = 0; rc < 8; rc++) {
        size_t base = ((size_t)rc * NDIM + col) * 3;
        top3_ins(g_cp[base + 0], r0, r1, r2);
        top3_ins(g_cp[base + 1], r0, r1, r2);
        top3_ins(g_cp[base + 2], r0, r1, r2);
    }
    g_t3c[col] = r2;
}

__global__ void assign_kernel(const float* __restrict__ S, float* __restrict__ outA)
{
    int i = blockIdx.x;
    float tr = g_t3r[i];
    const float* row = S + (size_t)i * MP1;
    float* arow = outA + (size_t)i * NDIM;
    for (int j = threadIdx.x; j < NDIM; j += 256) {
        float a = row[j];
        arow[j] = (a >= tr && a >= g_t3c[j] && a > THRESH) ? 1.0f : 0.0f;
    }
}

// ------------------------------- launcher ----------------------------------
extern "C" void kernel_launch(void* const* d_in, const int* in_sizes, int n_in,
                              void* d_out, int out_size)
{
    const float* desc0 = (const float*)d_in[0];
    const float* desc1 = (const float*)d_in[1];
    const float* W     = (const float*)d_in[2];
    const float* bias  = (const float*)d_in[3];
    const float* alpha = (const float*)d_in[4];

    float* outKn = (float*)d_out;
    float* outS  = outKn + (size_t)MDIM * NDIM;
    float* outA  = outS + (size_t)MP1 * MP1;

    int dev = 0, nsm = 0;
    cudaGetDevice(&dev);
    cudaDeviceGetAttribute(&nsm, cudaDevAttrMultiProcessorCount, dev);
    if (nsm <= 0) nsm = 148;

    // projections: (desc @ W^T + b) / s
    sgemm_nt<0><<<dim3(KDIM / 128, MDIM / 128), 256>>>(desc0, W, bias, nullptr);
    sgemm_nt<1><<<dim3(KDIM / 128, NDIM / 128), 256>>>(desc1, W, bias, nullptr);

    // dustbin row/col + V init + barrier reset
    init_kernel<<<(MP1 + 255) / 256, 256>>>(alpha);

    // Kn = m0s @ m1s^T  (+ exp epilogue into g_K fp32 + g_Kh fp16)
    sgemm_nt<2><<<dim3(NDIM / 128, MDIM / 128), 256>>>(nullptr, nullptr, nullptr, outKn);

    // persistent linear-domain Sinkhorn, 100 iterations (one block per SM)
    sinkhorn_persist<<<nsm, 512>>>(nsm);

    // scores = K * U * V * (m+n)  (+ row top-3)
    scores_kernel<<<MP1, 256>>>(outS);

    // mutual top-3 + threshold
    col_top3_part<<<dim3(NDIM / 32, 8), 256>>>(outS);
    col_top3_red<<<(NDIM + 255) / 256, 256>>>();
    assign_kernel<<<MDIM, 256>>>(outS, outA);
}